// round 13
// baseline (speedup 1.0000x reference)
#include <cuda_runtime.h>
#include <cuda_fp16.h>
#include <cstdint>

// ---------------------------------------------------------------------------
// xLSTM cell, fused, portable sm_103 path (no "a" features):
//   pass 1: convert x,h,W,U fp32 -> fp16 scratch (static __device__ buffers)
//   pass 2: G[8192,4096] = [x|h] @ [W|U]^T via mma.m16n8k16.f16, fp32 accum,
//           gating epilogue fused.
//
// R13 = best-of-R11/R12 consolidation + one refinement:
//   - warp_m step rotation REVERTED (R12 post-mortem: neutral-negative on
//     GEMM; lockstep-window theory falsified)
//   - segmented convert kernel KEPT (R12: 28 -> ~19us, DRAM floor)
//   - NEW: A(step0)-LDSM hoisted before the cp.async prefetch burst, so both
//     operand groups are in flight during the 8 cp.async issue slots and the
//     first MMA of each chunk starts ~20-30 cyc earlier (x32 chunks).
// Shape unchanged: two 256-thread CTAs/SM, CTA 128m x (4g x 32hc), warp
// 64x32, acc 64, 3-stage 32KB/stage, grid 2048 = 64m x 32h.
// ---------------------------------------------------------------------------

#define NTHREADS 256
#define STAGES 3
#define A_TILE_BYTES 16384            // 128 rows x 128B (64 fp16)
#define B_TILE_BYTES 16384            // 128 rows (4g x 32hc) x 128B
#define STAGE_BYTES  (A_TILE_BYTES + B_TILE_BYTES)   // 32768
#define SMEM_TOTAL   (STAGES * STAGE_BYTES)          // 98304

#define N_X 8388608                   // 8192*1024
#define N_W 4194304                   // 4*1024*1024

__device__ __align__(16) __half g_x16[N_X];
__device__ __align__(16) __half g_h16[N_X];
__device__ __align__(16) __half g_W16[N_W];
__device__ __align__(16) __half g_U16[N_W];

#define SWZ(o) ((o) ^ (((o) >> 3) & 0x70))

static __device__ __forceinline__ uint32_t smem_u32(const void* p) {
    uint32_t a;
    asm("{ .reg .u64 t; cvta.to.shared.u64 t, %1; cvt.u32.u64 %0, t; }"
        : "=r"(a) : "l"(p));
    return a;
}

#define CP_ASYNC16(dst, src) \
    asm volatile("cp.async.cg.shared.global [%0], [%1], 16;" :: "r"(dst), "l"(src) : "memory")
#define CP_COMMIT() asm volatile("cp.async.commit_group;" ::: "memory")
#define CP_WAIT1()  asm volatile("cp.async.wait_group 1;" ::: "memory")

#define LDMATRIX_X4(r0, r1, r2, r3, addr) \
    asm volatile("ldmatrix.sync.aligned.m8n8.x4.shared.b16 {%0,%1,%2,%3}, [%4];" \
                 : "=r"(r0), "=r"(r1), "=r"(r2), "=r"(r3) : "r"(addr))

#define MMA_F16(d, a, b0, b1) \
    asm volatile("mma.sync.aligned.m16n8k16.row.col.f32.f16.f16.f32 " \
                 "{%0,%1,%2,%3}, {%4,%5,%6,%7}, {%8,%9}, {%0,%1,%2,%3};" \
                 : "+f"((d)[0]), "+f"((d)[1]), "+f"((d)[2]), "+f"((d)[3]) \
                 : "r"((a)[0]), "r"((a)[1]), "r"((a)[2]), "r"((a)[3]), \
                   "r"(b0), "r"(b1))

static __device__ __forceinline__ float sigmoidf_(float v) {
    return 1.0f / (1.0f + __expf(-v));
}
static __device__ __forceinline__ float tanhf_(float v) {
    return 1.0f - 2.0f / (__expf(2.0f * v) + 1.0f);
}

// ---------------- pass 1: fp32 -> fp16 conversion (segmented) --------------
// float4 slots: x [0,2M), h [2M,4M), W [4M,5M), U [5M,6M). Block b covers
// contiguous slots [b*1024, (b+1)*1024); tensor select is block-uniform.
#define CVT_BLOCKS 6144
__global__ void __launch_bounds__(256) cvt_f32_to_f16_kernel(
    const float* __restrict__ x, const float* __restrict__ h,
    const float* __restrict__ W, const float* __restrict__ U)
{
    const long long n4x = N_X / 4;            // 2097152
    const long long n4w = N_W / 4;            // 1048576
    long long base = (long long)blockIdx.x * 1024;
    const float* s;
    __half* d;
    if (base < n4x)                       { s = x; d = g_x16; }
    else if (base < 2 * n4x)              { s = h; d = g_h16; base -= n4x; }
    else if (base < 2 * n4x + n4w)        { s = W; d = g_W16; base -= 2 * n4x; }
    else                                  { s = U; d = g_U16; base -= 2 * n4x + n4w; }
#pragma unroll
    for (int r = 0; r < 4; r++) {
        long long j = base + threadIdx.x + r * 256;
        float4 v = reinterpret_cast<const float4*>(s)[j];
        __half2 lo = __floats2half2_rn(v.x, v.y);
        __half2 hi = __floats2half2_rn(v.z, v.w);
        uint2 u;
        u.x = *reinterpret_cast<uint32_t*>(&lo);
        u.y = *reinterpret_cast<uint32_t*>(&hi);
        reinterpret_cast<uint2*>(d)[j] = u;
    }
}

// Load one BK=64 chunk (A 128x64 fp16 + B [4g x 32hc] x 64 fp16) into a stage.
static __device__ __forceinline__ void load_chunk64(
    int kc, uint32_t stage_sm,
    const uint32_t* dst, const int* srcA, const int* srcB)
{
    const __half* ap = (kc < 16) ? g_x16 : g_h16;
    const __half* bp = (kc < 16) ? g_W16 : g_U16;
    int k0 = (kc & 15) << 6;
    uint32_t sB = stage_sm + A_TILE_BYTES;
#pragma unroll
    for (int j = 0; j < 4; j++) CP_ASYNC16(stage_sm + dst[j], ap + srcA[j] + k0);
#pragma unroll
    for (int j = 0; j < 4; j++) CP_ASYNC16(sB + dst[j], bp + srcB[j] + k0);
}

// One BK=64 chunk: barrier -> B(kh0)+A(s0) LDSM -> prefetch -> 4 k16 steps
// (per step: grouped A-LDSM then 16 contiguous MMAs). CUR_ is a compile-time
// stage index (chunk kc uses stage kc%3; loop steps by 3).
#define STEP_MMAS(bs_) do {                                                  \
    _Pragma("unroll")                                                        \
    for (int mt = 0; mt < 4; mt++)                                           \
        _Pragma("unroll")                                                    \
        for (int g = 0; g < 4; g++)                                          \
            MMA_F16(acc[mt][g], afr[mt], bfr[g][bs_], bfr[g][(bs_) + 1]);    \
} while (0)

#define LOAD_AFR(sel_) do {                                                  \
    _Pragma("unroll")                                                        \
    for (int mt = 0; mt < 4; mt++)                                           \
        LDMATRIX_X4(afr[mt][0], afr[mt][1], afr[mt][2], afr[mt][3],          \
                    sA_ + aOff[mt] + (sel_));                                \
} while (0)

#define CHUNK_BODY(kc_, CUR_) do {                                           \
    CP_WAIT1();                                                              \
    __syncthreads();                                                         \
    const uint32_t sA_ = sbase + (uint32_t)((CUR_) * STAGE_BYTES);           \
    const uint32_t sB_ = sA_ + A_TILE_BYTES;                                 \
    uint32_t bfr[4][4];                                                      \
    uint32_t afr[4][4];                                                      \
    _Pragma("unroll")                                                        \
    for (int g = 0; g < 4; g++)                                              \
        LDMATRIX_X4(bfr[g][0], bfr[g][1], bfr[g][2], bfr[g][3],              \
                    sB_ + bOff[g] + bSel[0]);                                \
    LOAD_AFR(aSel[0]);                                                       \
    if ((kc_) + 2 < 32)                                                      \
        load_chunk64((kc_) + 2,                                              \
                     sbase + (uint32_t)((((CUR_) + 2) % 3) * STAGE_BYTES),   \
                     dst, srcA, srcB);                                       \
    CP_COMMIT();                                                             \
    STEP_MMAS(0);                                                            \
    LOAD_AFR(aSel[1]);                                                       \
    STEP_MMAS(2);                                                            \
    _Pragma("unroll")                                                        \
    for (int g = 0; g < 4; g++)                                              \
        LDMATRIX_X4(bfr[g][0], bfr[g][1], bfr[g][2], bfr[g][3],              \
                    sB_ + bOff[g] + bSel[1]);                                \
    LOAD_AFR(aSel[2]);                                                       \
    STEP_MMAS(0);                                                            \
    LOAD_AFR(aSel[3]);                                                       \
    STEP_MMAS(2);                                                            \
} while (0)

__global__ void __launch_bounds__(NTHREADS, 2) xlstm_f16_mma_kernel(
    const float* __restrict__ cprev,
    const float* __restrict__ bW, const float* __restrict__ bU,
    float* __restrict__ o1, float* __restrict__ o2, float* __restrict__ oc)
{
    extern __shared__ char smem[];
    const uint32_t sbase = smem_u32(smem);

    const int tid  = threadIdx.x;
    const int lane = tid & 31;
    const int warp = tid >> 5;
    const int warp_m = warp >> 2;      // 0..1 : 64 m-rows each
    const int warp_n = warp & 3;       // 0..3 : 8 h-cols each (x4 gates)

    const int bid = blockIdx.x;
    const int m0 = (bid >> 5) << 7;    // 64 m-tiles of 128
    const int h0 = (bid & 31) << 5;    // 32 h-tiles of 32

    // ---- cp.async per-thread offsets (slot j: row r = slot/8, 16B chunk cq) ----
    uint32_t dst[4];
    int srcA[4], srcB[4];
#pragma unroll
    for (int j = 0; j < 4; j++) {
        int slot = tid + j * NTHREADS;       // 0..1023
        int r = slot >> 3, cq = slot & 7;
        dst[j] = SWZ((uint32_t)(r * 128 + cq * 16));
        srcA[j] = (m0 + r) * 1024 + cq * 8;
        int g = r >> 5, hc = r & 31;         // B rows: gate-major [4][32]
        srcB[j] = g * 1048576 + (h0 + hc) * 1024 + cq * 8;
    }

    // ---- ldmatrix per-thread address components ----
    const uint32_t xorv = (uint32_t)(lane & 7) << 4;
    uint32_t aOff[4];
#pragma unroll
    for (int mt = 0; mt < 4; mt++)
        aOff[mt] = (uint32_t)(warp_m * 64 + mt * 16 + (lane & 15)) * 128u;
    uint32_t aSel[4];
#pragma unroll
    for (int s = 0; s < 4; s++)
        aSel[s] = ((uint32_t)(s * 32) + ((uint32_t)(lane >> 4) << 4)) ^ xorv;
    uint32_t bOff[4];
#pragma unroll
    for (int g = 0; g < 4; g++)
        bOff[g] = (uint32_t)(g * 32 + warp_n * 8 + (lane & 7)) * 128u;
    uint32_t bSel[2];
#pragma unroll
    for (int kh = 0; kh < 2; kh++)
        bSel[kh] = ((uint32_t)(kh * 64) + ((uint32_t)(lane >> 3) << 4)) ^ xorv;

    float acc[4][4][4];   // [mt][gate][frag]
#pragma unroll
    for (int mt = 0; mt < 4; mt++)
#pragma unroll
        for (int g = 0; g < 4; g++)
#pragma unroll
            for (int r = 0; r < 4; r++) acc[mt][g][r] = 0.0f;

    // ---- prologue: chunks 0,1 into stages 0,1 ----
    load_chunk64(0, sbase, dst, srcA, srcB);
    CP_COMMIT();
    load_chunk64(1, sbase + STAGE_BYTES, dst, srcA, srcB);
    CP_COMMIT();

    // ---- mainloop: 32 BK=64 chunks, stage = chunk % 3 (compile-time) ----
#pragma unroll 1
    for (int kc = 0; kc < 32; kc += 3) {
        CHUNK_BODY(kc, 0);
        CHUNK_BODY(kc + 1, 1);
        if (kc + 2 < 32) CHUNK_BODY(kc + 2, 2);
    }

    // ---- epilogue: thread-local (all 4 gates of each (m,h) in this thread) ----
    const int hc0 = h0 + warp_n * 8 + 2 * (lane & 3);

    float bsum[4][2];
#pragma unroll
    for (int g = 0; g < 4; g++)
#pragma unroll
        for (int e = 0; e < 2; e++)
            bsum[g][e] = bW[g * 1024 + hc0 + e] + bU[g * 1024 + hc0 + e];

#pragma unroll
    for (int mt = 0; mt < 4; mt++) {
#pragma unroll
        for (int rh = 0; rh < 2; rh++) {
            int m = m0 + warp_m * 64 + mt * 16 + (lane >> 2) + rh * 8;
            size_t base = (size_t)m * 1024 + hc0;
            float2 cold = *reinterpret_cast<const float2*>(cprev + base);

            float hn[2], cn[2];
#pragma unroll
            for (int e = 0; e < 2; e++) {
                int rr = rh * 2 + e;
                float gi = acc[mt][0][rr] + bsum[0][e];
                float gf = acc[mt][1][rr] + bsum[1][e];
                float go = acc[mt][2][rr] + bsum[2][e];
                float gc = acc[mt][3][rr] + bsum[3][e];
                float iv = sigmoidf_(gi);
                float fv = sigmoidf_(gf);
                float ov = sigmoidf_(go);
                float ch = tanhf_(gc);
                float cold_e = (e == 0) ? cold.x : cold.y;
                float cv = fv * cold_e + iv * ch;
                cn[e] = cv;
                hn[e] = ov * tanhf_(cv);
            }

            float2 hv = make_float2(hn[0], hn[1]);
            *reinterpret_cast<float2*>(o1 + base) = hv;
            if (o2) *reinterpret_cast<float2*>(o2 + base) = hv;
            if (oc) *reinterpret_cast<float2*>(oc + base) = make_float2(cn[0], cn[1]);
        }
    }
}

extern "C" void kernel_launch(void* const* d_in, const int* in_sizes, int n_in,
                              void* d_out, int out_size) {
    const float* x  = (const float*)d_in[0];
    const float* h  = (const float*)d_in[1];
    const float* c  = (const float*)d_in[2];
    const float* W  = (const float*)d_in[3];
    const float* bW = (const float*)d_in[4];
    const float* U  = (const float*)d_in[5];
    const float* bU = (const float*)d_in[6];
    float* out = (float*)d_out;

    const long long BH = 8192LL * 1024LL;
    float* o1 = out;
    float* o2 = nullptr;
    float* oc = nullptr;
    if ((long long)out_size >= 3 * BH) {          // (h_new, h_new, c_new)
        o2 = out + BH;
        oc = out + 2 * BH;
    } else if ((long long)out_size >= 2 * BH) {   // (h_new, c_new)
        oc = out + BH;
    }

    cvt_f32_to_f16_kernel<<<CVT_BLOCKS, 256>>>(x, h, W, U);

    cudaFuncSetAttribute(xlstm_f16_mma_kernel,
                         cudaFuncAttributeMaxDynamicSharedMemorySize, SMEM_TOTAL);
    xlstm_f16_mma_kernel<<<2048, NTHREADS, SMEM_TOTAL>>>(c, bW, bU, o1, o2, oc);
}

// round 14
// speedup vs baseline: 1.0393x; 1.0393x over previous
#include <cuda_runtime.h>
#include <cuda_fp16.h>
#include <cstdint>

// ---------------------------------------------------------------------------
// xLSTM cell, fused, portable sm_103 path (no "a" features):
//   pass 1: convert x,h,W,U fp32 -> fp16 scratch (static __device__ buffers)
//   pass 2: G[8192,4096] = [x|h] @ [W|U]^T via mma.m16n8k16.f16, fp32 accum,
//           gating epilogue fused.
//
// R14 = consolidation of the two measured-best components:
//   - GEMM: exact R11 chunk body (334.9us GEMM, tensor=67.4%). R6/R12/R13
//     each tried to reorder this body and ALL regressed -> it is final.
//   - convert: R12 segmented kernel (~19us, DRAM floor).
// Shape: two 256-thread CTAs/SM, CTA 128m x (4g x 32hc), warp 64x32, acc 64,
// 3-stage 32KB/stage (compile-time stage idx via unroll-by-3), grid 2048.
// ---------------------------------------------------------------------------

#define NTHREADS 256
#define STAGES 3
#define A_TILE_BYTES 16384            // 128 rows x 128B (64 fp16)
#define B_TILE_BYTES 16384            // 128 rows (4g x 32hc) x 128B
#define STAGE_BYTES  (A_TILE_BYTES + B_TILE_BYTES)   // 32768
#define SMEM_TOTAL   (STAGES * STAGE_BYTES)          // 98304

#define N_X 8388608                   // 8192*1024
#define N_W 4194304                   // 4*1024*1024

__device__ __align__(16) __half g_x16[N_X];
__device__ __align__(16) __half g_h16[N_X];
__device__ __align__(16) __half g_W16[N_W];
__device__ __align__(16) __half g_U16[N_W];

#define SWZ(o) ((o) ^ (((o) >> 3) & 0x70))

static __device__ __forceinline__ uint32_t smem_u32(const void* p) {
    uint32_t a;
    asm("{ .reg .u64 t; cvta.to.shared.u64 t, %1; cvt.u32.u64 %0, t; }"
        : "=r"(a) : "l"(p));
    return a;
}

#define CP_ASYNC16(dst, src) \
    asm volatile("cp.async.cg.shared.global [%0], [%1], 16;" :: "r"(dst), "l"(src) : "memory")
#define CP_COMMIT() asm volatile("cp.async.commit_group;" ::: "memory")
#define CP_WAIT1()  asm volatile("cp.async.wait_group 1;" ::: "memory")

#define LDMATRIX_X4(r0, r1, r2, r3, addr) \
    asm volatile("ldmatrix.sync.aligned.m8n8.x4.shared.b16 {%0,%1,%2,%3}, [%4];" \
                 : "=r"(r0), "=r"(r1), "=r"(r2), "=r"(r3) : "r"(addr))

#define MMA_F16(d, a, b0, b1) \
    asm volatile("mma.sync.aligned.m16n8k16.row.col.f32.f16.f16.f32 " \
                 "{%0,%1,%2,%3}, {%4,%5,%6,%7}, {%8,%9}, {%0,%1,%2,%3};" \
                 : "+f"((d)[0]), "+f"((d)[1]), "+f"((d)[2]), "+f"((d)[3]) \
                 : "r"((a)[0]), "r"((a)[1]), "r"((a)[2]), "r"((a)[3]), \
                   "r"(b0), "r"(b1))

static __device__ __forceinline__ float sigmoidf_(float v) {
    return 1.0f / (1.0f + __expf(-v));
}
static __device__ __forceinline__ float tanhf_(float v) {
    return 1.0f - 2.0f / (__expf(2.0f * v) + 1.0f);
}

// ---------------- pass 1: fp32 -> fp16 conversion (segmented) --------------
// float4 slots: x [0,2M), h [2M,4M), W [4M,5M), U [5M,6M). Block b covers
// contiguous slots [b*1024, (b+1)*1024); tensor select is block-uniform.
#define CVT_BLOCKS 6144
__global__ void __launch_bounds__(256) cvt_f32_to_f16_kernel(
    const float* __restrict__ x, const float* __restrict__ h,
    const float* __restrict__ W, const float* __restrict__ U)
{
    const long long n4x = N_X / 4;            // 2097152
    const long long n4w = N_W / 4;            // 1048576
    long long base = (long long)blockIdx.x * 1024;
    const float* s;
    __half* d;
    if (base < n4x)                       { s = x; d = g_x16; }
    else if (base < 2 * n4x)              { s = h; d = g_h16; base -= n4x; }
    else if (base < 2 * n4x + n4w)        { s = W; d = g_W16; base -= 2 * n4x; }
    else                                  { s = U; d = g_U16; base -= 2 * n4x + n4w; }
#pragma unroll
    for (int r = 0; r < 4; r++) {
        long long j = base + threadIdx.x + r * 256;
        float4 v = reinterpret_cast<const float4*>(s)[j];
        __half2 lo = __floats2half2_rn(v.x, v.y);
        __half2 hi = __floats2half2_rn(v.z, v.w);
        uint2 u;
        u.x = *reinterpret_cast<uint32_t*>(&lo);
        u.y = *reinterpret_cast<uint32_t*>(&hi);
        reinterpret_cast<uint2*>(d)[j] = u;
    }
}

// Load one BK=64 chunk (A 128x64 fp16 + B [4g x 32hc] x 64 fp16) into a stage.
static __device__ __forceinline__ void load_chunk64(
    int kc, uint32_t stage_sm,
    const uint32_t* dst, const int* srcA, const int* srcB)
{
    const __half* ap = (kc < 16) ? g_x16 : g_h16;
    const __half* bp = (kc < 16) ? g_W16 : g_U16;
    int k0 = (kc & 15) << 6;
    uint32_t sB = stage_sm + A_TILE_BYTES;
#pragma unroll
    for (int j = 0; j < 4; j++) CP_ASYNC16(stage_sm + dst[j], ap + srcA[j] + k0);
#pragma unroll
    for (int j = 0; j < 4; j++) CP_ASYNC16(sB + dst[j], bp + srcB[j] + k0);
}

// One BK=64 chunk (EXACT R11 body): barrier, B(kh0) LDSM, prefetch, then per
// k16 step: 4 grouped A-LDSM, then 16 contiguous MMAs. CUR_ is a compile-time
// stage index (chunk kc uses stage kc%3; loop steps by 3).
#define CHUNK_BODY(kc_, CUR_) do {                                           \
    CP_WAIT1();                                                              \
    __syncthreads();                                                         \
    const uint32_t sA_ = sbase + (uint32_t)((CUR_) * STAGE_BYTES);           \
    const uint32_t sB_ = sA_ + A_TILE_BYTES;                                 \
    uint32_t bfr[4][4];                                                      \
    _Pragma("unroll")                                                        \
    for (int g = 0; g < 4; g++)                                              \
        LDMATRIX_X4(bfr[g][0], bfr[g][1], bfr[g][2], bfr[g][3],              \
                    sB_ + bOff[g] + bSel[0]);                                \
    if ((kc_) + 2 < 32)                                                      \
        load_chunk64((kc_) + 2,                                              \
                     sbase + (uint32_t)((((CUR_) + 2) % 3) * STAGE_BYTES),   \
                     dst, srcA, srcB);                                       \
    CP_COMMIT();                                                             \
    _Pragma("unroll")                                                        \
    for (int kh = 0; kh < 2; kh++) {                                         \
        if (kh == 1) {                                                       \
            _Pragma("unroll")                                                \
            for (int g = 0; g < 4; g++)                                      \
                LDMATRIX_X4(bfr[g][0], bfr[g][1], bfr[g][2], bfr[g][3],      \
                            sB_ + bOff[g] + bSel[1]);                        \
        }                                                                    \
        _Pragma("unroll")                                                    \
        for (int t = 0; t < 2; t++) {                                        \
            const uint32_t aCh = aSel[kh * 2 + t];                           \
            const int bs = t << 1;                                           \
            uint32_t afr[4][4];                                              \
            _Pragma("unroll")                                                \
            for (int mt = 0; mt < 4; mt++)                                   \
                LDMATRIX_X4(afr[mt][0], afr[mt][1], afr[mt][2], afr[mt][3],  \
                            sA_ + aOff[mt] + aCh);                           \
            _Pragma("unroll")                                                \
            for (int mt = 0; mt < 4; mt++)                                   \
                _Pragma("unroll")                                            \
                for (int g = 0; g < 4; g++)                                  \
                    MMA_F16(acc[mt][g], afr[mt], bfr[g][bs], bfr[g][bs + 1]);\
        }                                                                    \
    }                                                                        \
} while (0)

__global__ void __launch_bounds__(NTHREADS, 2) xlstm_f16_mma_kernel(
    const float* __restrict__ cprev,
    const float* __restrict__ bW, const float* __restrict__ bU,
    float* __restrict__ o1, float* __restrict__ o2, float* __restrict__ oc)
{
    extern __shared__ char smem[];
    const uint32_t sbase = smem_u32(smem);

    const int tid  = threadIdx.x;
    const int lane = tid & 31;
    const int warp = tid >> 5;
    const int warp_m = warp >> 2;      // 0..1 : 64 m-rows each
    const int warp_n = warp & 3;       // 0..3 : 8 h-cols each (x4 gates)

    const int bid = blockIdx.x;
    const int m0 = (bid >> 5) << 7;    // 64 m-tiles of 128
    const int h0 = (bid & 31) << 5;    // 32 h-tiles of 32

    // ---- cp.async per-thread offsets (slot j: row r = slot/8, 16B chunk cq) ----
    uint32_t dst[4];
    int srcA[4], srcB[4];
#pragma unroll
    for (int j = 0; j < 4; j++) {
        int slot = tid + j * NTHREADS;       // 0..1023
        int r = slot >> 3, cq = slot & 7;
        dst[j] = SWZ((uint32_t)(r * 128 + cq * 16));
        srcA[j] = (m0 + r) * 1024 + cq * 8;
        int g = r >> 5, hc = r & 31;         // B rows: gate-major [4][32]
        srcB[j] = g * 1048576 + (h0 + hc) * 1024 + cq * 8;
    }

    // ---- ldmatrix per-thread address components ----
    const uint32_t xorv = (uint32_t)(lane & 7) << 4;
    uint32_t aOff[4];
#pragma unroll
    for (int mt = 0; mt < 4; mt++)
        aOff[mt] = (uint32_t)(warp_m * 64 + mt * 16 + (lane & 15)) * 128u;
    uint32_t aSel[4];
#pragma unroll
    for (int s = 0; s < 4; s++)
        aSel[s] = ((uint32_t)(s * 32) + ((uint32_t)(lane >> 4) << 4)) ^ xorv;
    uint32_t bOff[4];
#pragma unroll
    for (int g = 0; g < 4; g++)
        bOff[g] = (uint32_t)(g * 32 + warp_n * 8 + (lane & 7)) * 128u;
    uint32_t bSel[2];
#pragma unroll
    for (int kh = 0; kh < 2; kh++)
        bSel[kh] = ((uint32_t)(kh * 64) + ((uint32_t)(lane >> 3) << 4)) ^ xorv;

    float acc[4][4][4];   // [mt][gate][frag]
#pragma unroll
    for (int mt = 0; mt < 4; mt++)
#pragma unroll
        for (int g = 0; g < 4; g++)
#pragma unroll
            for (int r = 0; r < 4; r++) acc[mt][g][r] = 0.0f;

    // ---- prologue: chunks 0,1 into stages 0,1 ----
    load_chunk64(0, sbase, dst, srcA, srcB);
    CP_COMMIT();
    load_chunk64(1, sbase + STAGE_BYTES, dst, srcA, srcB);
    CP_COMMIT();

    // ---- mainloop: 32 BK=64 chunks, stage = chunk % 3 (compile-time) ----
#pragma unroll 1
    for (int kc = 0; kc < 32; kc += 3) {
        CHUNK_BODY(kc, 0);
        CHUNK_BODY(kc + 1, 1);
        if (kc + 2 < 32) CHUNK_BODY(kc + 2, 2);
    }

    // ---- epilogue: thread-local (all 4 gates of each (m,h) in this thread) ----
    const int hc0 = h0 + warp_n * 8 + 2 * (lane & 3);

    float bsum[4][2];
#pragma unroll
    for (int g = 0; g < 4; g++)
#pragma unroll
        for (int e = 0; e < 2; e++)
            bsum[g][e] = bW[g * 1024 + hc0 + e] + bU[g * 1024 + hc0 + e];

#pragma unroll
    for (int mt = 0; mt < 4; mt++) {
#pragma unroll
        for (int rh = 0; rh < 2; rh++) {
            int m = m0 + warp_m * 64 + mt * 16 + (lane >> 2) + rh * 8;
            size_t base = (size_t)m * 1024 + hc0;
            float2 cold = *reinterpret_cast<const float2*>(cprev + base);

            float hn[2], cn[2];
#pragma unroll
            for (int e = 0; e < 2; e++) {
                int rr = rh * 2 + e;
                float gi = acc[mt][0][rr] + bsum[0][e];
                float gf = acc[mt][1][rr] + bsum[1][e];
                float go = acc[mt][2][rr] + bsum[2][e];
                float gc = acc[mt][3][rr] + bsum[3][e];
                float iv = sigmoidf_(gi);
                float fv = sigmoidf_(gf);
                float ov = sigmoidf_(go);
                float ch = tanhf_(gc);
                float cold_e = (e == 0) ? cold.x : cold.y;
                float cv = fv * cold_e + iv * ch;
                cn[e] = cv;
                hn[e] = ov * tanhf_(cv);
            }

            float2 hv = make_float2(hn[0], hn[1]);
            *reinterpret_cast<float2*>(o1 + base) = hv;
            if (o2) *reinterpret_cast<float2*>(o2 + base) = hv;
            if (oc) *reinterpret_cast<float2*>(oc + base) = make_float2(cn[0], cn[1]);
        }
    }
}

extern "C" void kernel_launch(void* const* d_in, const int* in_sizes, int n_in,
                              void* d_out, int out_size) {
    const float* x  = (const float*)d_in[0];
    const float* h  = (const float*)d_in[1];
    const float* c  = (const float*)d_in[2];
    const float* W  = (const float*)d_in[3];
    const float* bW = (const float*)d_in[4];
    const float* U  = (const float*)d_in[5];
    const float* bU = (const float*)d_in[6];
    float* out = (float*)d_out;

    const long long BH = 8192LL * 1024LL;
    float* o1 = out;
    float* o2 = nullptr;
    float* oc = nullptr;
    if ((long long)out_size >= 3 * BH) {          // (h_new, h_new, c_new)
        o2 = out + BH;
        oc = out + 2 * BH;
    } else if ((long long)out_size >= 2 * BH) {   // (h_new, c_new)
        oc = out + BH;
    }

    cvt_f32_to_f16_kernel<<<CVT_BLOCKS, 256>>>(x, h, W, U);

    cudaFuncSetAttribute(xlstm_f16_mma_kernel,
                         cudaFuncAttributeMaxDynamicSharedMemorySize, SMEM_TOTAL);
    xlstm_f16_mma_kernel<<<2048, NTHREADS, SMEM_TOTAL>>>(c, bW, bU, o1, o2, oc);
}

// round 15
// speedup vs baseline: 1.0394x; 1.0001x over previous
#include <cuda_runtime.h>
#include <cuda_fp16.h>
#include <cstdint>

// ---------------------------------------------------------------------------
// xLSTM cell, fused, portable sm_103 path (no "a" features):
//   pass 1: convert x,h,W,U fp32 -> fp16 scratch (static __device__ buffers)
//   pass 2: G[8192,4096] = [x|h] @ [W|U]^T via mma.m16n8k16.f16, fp32 accum,
//           gating epilogue fused.
//
// R15 = R14 (best, 356.4us) with the GEMM kernel FROZEN (measured optimum:
// R6/R12/R13 body reorders and R8/R9 shape changes all regressed; smem BW,
// tensor pipe and occupancy are co-balanced at tensor=67.5%) + a tightened
// convert pass: 2 consecutive float4 reads -> 1 uint4 store per thread-iter
// (half the store instructions, same perfect coalescing).
// GEMM shape: two 256-thread CTAs/SM, CTA 128m x (4g x 32hc), warp 64x32,
// acc 64, 3-stage 32KB/stage (compile-time stage idx), grid 2048 = 64m x 32h.
// ---------------------------------------------------------------------------

#define NTHREADS 256
#define STAGES 3
#define A_TILE_BYTES 16384            // 128 rows x 128B (64 fp16)
#define B_TILE_BYTES 16384            // 128 rows (4g x 32hc) x 128B
#define STAGE_BYTES  (A_TILE_BYTES + B_TILE_BYTES)   // 32768
#define SMEM_TOTAL   (STAGES * STAGE_BYTES)          // 98304

#define N_X 8388608                   // 8192*1024
#define N_W 4194304                   // 4*1024*1024

__device__ __align__(16) __half g_x16[N_X];
__device__ __align__(16) __half g_h16[N_X];
__device__ __align__(16) __half g_W16[N_W];
__device__ __align__(16) __half g_U16[N_W];

#define SWZ(o) ((o) ^ (((o) >> 3) & 0x70))

static __device__ __forceinline__ uint32_t smem_u32(const void* p) {
    uint32_t a;
    asm("{ .reg .u64 t; cvta.to.shared.u64 t, %1; cvt.u32.u64 %0, t; }"
        : "=r"(a) : "l"(p));
    return a;
}

#define CP_ASYNC16(dst, src) \
    asm volatile("cp.async.cg.shared.global [%0], [%1], 16;" :: "r"(dst), "l"(src) : "memory")
#define CP_COMMIT() asm volatile("cp.async.commit_group;" ::: "memory")
#define CP_WAIT1()  asm volatile("cp.async.wait_group 1;" ::: "memory")

#define LDMATRIX_X4(r0, r1, r2, r3, addr) \
    asm volatile("ldmatrix.sync.aligned.m8n8.x4.shared.b16 {%0,%1,%2,%3}, [%4];" \
                 : "=r"(r0), "=r"(r1), "=r"(r2), "=r"(r3) : "r"(addr))

#define MMA_F16(d, a, b0, b1) \
    asm volatile("mma.sync.aligned.m16n8k16.row.col.f32.f16.f16.f32 " \
                 "{%0,%1,%2,%3}, {%4,%5,%6,%7}, {%8,%9}, {%0,%1,%2,%3};" \
                 : "+f"((d)[0]), "+f"((d)[1]), "+f"((d)[2]), "+f"((d)[3]) \
                 : "r"((a)[0]), "r"((a)[1]), "r"((a)[2]), "r"((a)[3]), \
                   "r"(b0), "r"(b1))

static __device__ __forceinline__ float sigmoidf_(float v) {
    return 1.0f / (1.0f + __expf(-v));
}
static __device__ __forceinline__ float tanhf_(float v) {
    return 1.0f - 2.0f / (__expf(2.0f * v) + 1.0f);
}

// ---------------- pass 1: fp32 -> fp16 conversion (segmented, uint4) -------
// float4 slots: x [0,2M), h [2M,4M), W [4M,5M), U [5M,6M). Block b covers
// contiguous slots [b*2048, (b+1)*2048); all segment sizes divide by 2048 so
// tensor select is block-uniform. Per iter: thread reads 2 consecutive
// float4 (32B) and writes 1 uint4 (16B of fp16).
#define CVT_BLOCKS 3072
__global__ void __launch_bounds__(256) cvt_f32_to_f16_kernel(
    const float* __restrict__ x, const float* __restrict__ h,
    const float* __restrict__ W, const float* __restrict__ U)
{
    const long long n4x = N_X / 4;            // 2097152
    const long long n4w = N_W / 4;            // 1048576
    long long base = (long long)blockIdx.x * 2048;
    const float* s;
    __half* d;
    if (base < n4x)                       { s = x; d = g_x16; }
    else if (base < 2 * n4x)              { s = h; d = g_h16; base -= n4x; }
    else if (base < 2 * n4x + n4w)        { s = W; d = g_W16; base -= 2 * n4x; }
    else                                  { s = U; d = g_U16; base -= 2 * n4x + n4w; }
#pragma unroll
    for (int r = 0; r < 4; r++) {
        long long j = base + ((long long)threadIdx.x + r * 256) * 2;
        float4 v0 = reinterpret_cast<const float4*>(s)[j];
        float4 v1 = reinterpret_cast<const float4*>(s)[j + 1];
        __half2 p0 = __floats2half2_rn(v0.x, v0.y);
        __half2 p1 = __floats2half2_rn(v0.z, v0.w);
        __half2 p2 = __floats2half2_rn(v1.x, v1.y);
        __half2 p3 = __floats2half2_rn(v1.z, v1.w);
        uint4 u;
        u.x = *reinterpret_cast<uint32_t*>(&p0);
        u.y = *reinterpret_cast<uint32_t*>(&p1);
        u.z = *reinterpret_cast<uint32_t*>(&p2);
        u.w = *reinterpret_cast<uint32_t*>(&p3);
        reinterpret_cast<uint4*>(d)[j >> 1] = u;
    }
}

// Load one BK=64 chunk (A 128x64 fp16 + B [4g x 32hc] x 64 fp16) into a stage.
static __device__ __forceinline__ void load_chunk64(
    int kc, uint32_t stage_sm,
    const uint32_t* dst, const int* srcA, const int* srcB)
{
    const __half* ap = (kc < 16) ? g_x16 : g_h16;
    const __half* bp = (kc < 16) ? g_W16 : g_U16;
    int k0 = (kc & 15) << 6;
    uint32_t sB = stage_sm + A_TILE_BYTES;
#pragma unroll
    for (int j = 0; j < 4; j++) CP_ASYNC16(stage_sm + dst[j], ap + srcA[j] + k0);
#pragma unroll
    for (int j = 0; j < 4; j++) CP_ASYNC16(sB + dst[j], bp + srcB[j] + k0);
}

// One BK=64 chunk (FROZEN R11/R14 body): barrier, B(kh0) LDSM, prefetch,
// then per k16 step: 4 grouped A-LDSM, then 16 contiguous MMAs. CUR_ is a
// compile-time stage index (chunk kc uses stage kc%3; loop steps by 3).
#define CHUNK_BODY(kc_, CUR_) do {                                           \
    CP_WAIT1();                                                              \
    __syncthreads();                                                         \
    const uint32_t sA_ = sbase + (uint32_t)((CUR_) * STAGE_BYTES);           \
    const uint32_t sB_ = sA_ + A_TILE_BYTES;                                 \
    uint32_t bfr[4][4];                                                      \
    _Pragma("unroll")                                                        \
    for (int g = 0; g < 4; g++)                                              \
        LDMATRIX_X4(bfr[g][0], bfr[g][1], bfr[g][2], bfr[g][3],              \
                    sB_ + bOff[g] + bSel[0]);                                \
    if ((kc_) + 2 < 32)                                                      \
        load_chunk64((kc_) + 2,                                              \
                     sbase + (uint32_t)((((CUR_) + 2) % 3) * STAGE_BYTES),   \
                     dst, srcA, srcB);                                       \
    CP_COMMIT();                                                             \
    _Pragma("unroll")                                                        \
    for (int kh = 0; kh < 2; kh++) {                                         \
        if (kh == 1) {                                                       \
            _Pragma("unroll")                                                \
            for (int g = 0; g < 4; g++)                                      \
                LDMATRIX_X4(bfr[g][0], bfr[g][1], bfr[g][2], bfr[g][3],      \
                            sB_ + bOff[g] + bSel[1]);                        \
        }                                                                    \
        _Pragma("unroll")                                                    \
        for (int t = 0; t < 2; t++) {                                        \
            const uint32_t aCh = aSel[kh * 2 + t];                           \
            const int bs = t << 1;                                           \
            uint32_t afr[4][4];                                              \
            _Pragma("unroll")                                                \
            for (int mt = 0; mt < 4; mt++)                                   \
                LDMATRIX_X4(afr[mt][0], afr[mt][1], afr[mt][2], afr[mt][3],  \
                            sA_ + aOff[mt] + aCh);                           \
            _Pragma("unroll")                                                \
            for (int mt = 0; mt < 4; mt++)                                   \
                _Pragma("unroll")                                            \
                for (int g = 0; g < 4; g++)                                  \
                    MMA_F16(acc[mt][g], afr[mt], bfr[g][bs], bfr[g][bs + 1]);\
        }                                                                    \
    }                                                                        \
} while (0)

__global__ void __launch_bounds__(NTHREADS, 2) xlstm_f16_mma_kernel(
    const float* __restrict__ cprev,
    const float* __restrict__ bW, const float* __restrict__ bU,
    float* __restrict__ o1, float* __restrict__ o2, float* __restrict__ oc)
{
    extern __shared__ char smem[];
    const uint32_t sbase = smem_u32(smem);

    const int tid  = threadIdx.x;
    const int lane = tid & 31;
    const int warp = tid >> 5;
    const int warp_m = warp >> 2;      // 0..1 : 64 m-rows each
    const int warp_n = warp & 3;       // 0..3 : 8 h-cols each (x4 gates)

    const int bid = blockIdx.x;
    const int m0 = (bid >> 5) << 7;    // 64 m-tiles of 128
    const int h0 = (bid & 31) << 5;    // 32 h-tiles of 32

    // ---- cp.async per-thread offsets (slot j: row r = slot/8, 16B chunk cq) ----
    uint32_t dst[4];
    int srcA[4], srcB[4];
#pragma unroll
    for (int j = 0; j < 4; j++) {
        int slot = tid + j * NTHREADS;       // 0..1023
        int r = slot >> 3, cq = slot & 7;
        dst[j] = SWZ((uint32_t)(r * 128 + cq * 16));
        srcA[j] = (m0 + r) * 1024 + cq * 8;
        int g = r >> 5, hc = r & 31;         // B rows: gate-major [4][32]
        srcB[j] = g * 1048576 + (h0 + hc) * 1024 + cq * 8;
    }

    // ---- ldmatrix per-thread address components ----
    const uint32_t xorv = (uint32_t)(lane & 7) << 4;
    uint32_t aOff[4];
#pragma unroll
    for (int mt = 0; mt < 4; mt++)
        aOff[mt] = (uint32_t)(warp_m * 64 + mt * 16 + (lane & 15)) * 128u;
    uint32_t aSel[4];
#pragma unroll
    for (int s = 0; s < 4; s++)
        aSel[s] = ((uint32_t)(s * 32) + ((uint32_t)(lane >> 4) << 4)) ^ xorv;
    uint32_t bOff[4];
#pragma unroll
    for (int g = 0; g < 4; g++)
        bOff[g] = (uint32_t)(g * 32 + warp_n * 8 + (lane & 7)) * 128u;
    uint32_t bSel[2];
#pragma unroll
    for (int kh = 0; kh < 2; kh++)
        bSel[kh] = ((uint32_t)(kh * 64) + ((uint32_t)(lane >> 3) << 4)) ^ xorv;

    float acc[4][4][4];   // [mt][gate][frag]
#pragma unroll
    for (int mt = 0; mt < 4; mt++)
#pragma unroll
        for (int g = 0; g < 4; g++)
#pragma unroll
            for (int r = 0; r < 4; r++) acc[mt][g][r] = 0.0f;

    // ---- prologue: chunks 0,1 into stages 0,1 ----
    load_chunk64(0, sbase, dst, srcA, srcB);
    CP_COMMIT();
    load_chunk64(1, sbase + STAGE_BYTES, dst, srcA, srcB);
    CP_COMMIT();

    // ---- mainloop: 32 BK=64 chunks, stage = chunk % 3 (compile-time) ----
#pragma unroll 1
    for (int kc = 0; kc < 32; kc += 3) {
        CHUNK_BODY(kc, 0);
        CHUNK_BODY(kc + 1, 1);
        if (kc + 2 < 32) CHUNK_BODY(kc + 2, 2);
    }

    // ---- epilogue: thread-local (all 4 gates of each (m,h) in this thread) ----
    const int hc0 = h0 + warp_n * 8 + 2 * (lane & 3);

    float bsum[4][2];
#pragma unroll
    for (int g = 0; g < 4; g++)
#pragma unroll
        for (int e = 0; e < 2; e++)
            bsum[g][e] = bW[g * 1024 + hc0 + e] + bU[g * 1024 + hc0 + e];

#pragma unroll
    for (int mt = 0; mt < 4; mt++) {
#pragma unroll
        for (int rh = 0; rh < 2; rh++) {
            int m = m0 + warp_m * 64 + mt * 16 + (lane >> 2) + rh * 8;
            size_t base = (size_t)m * 1024 + hc0;
            float2 cold = *reinterpret_cast<const float2*>(cprev + base);

            float hn[2], cn[2];
#pragma unroll
            for (int e = 0; e < 2; e++) {
                int rr = rh * 2 + e;
                float gi = acc[mt][0][rr] + bsum[0][e];
                float gf = acc[mt][1][rr] + bsum[1][e];
                float go = acc[mt][2][rr] + bsum[2][e];
                float gc = acc[mt][3][rr] + bsum[3][e];
                float iv = sigmoidf_(gi);
                float fv = sigmoidf_(gf);
                float ov = sigmoidf_(go);
                float ch = tanhf_(gc);
                float cold_e = (e == 0) ? cold.x : cold.y;
                float cv = fv * cold_e + iv * ch;
                cn[e] = cv;
                hn[e] = ov * tanhf_(cv);
            }

            float2 hv = make_float2(hn[0], hn[1]);
            *reinterpret_cast<float2*>(o1 + base) = hv;
            if (o2) *reinterpret_cast<float2*>(o2 + base) = hv;
            if (oc) *reinterpret_cast<float2*>(oc + base) = make_float2(cn[0], cn[1]);
        }
    }
}

extern "C" void kernel_launch(void* const* d_in, const int* in_sizes, int n_in,
                              void* d_out, int out_size) {
    const float* x  = (const float*)d_in[0];
    const float* h  = (const float*)d_in[1];
    const float* c  = (const float*)d_in[2];
    const float* W  = (const float*)d_in[3];
    const float* bW = (const float*)d_in[4];
    const float* U  = (const float*)d_in[5];
    const float* bU = (const float*)d_in[6];
    float* out = (float*)d_out;

    const long long BH = 8192LL * 1024LL;
    float* o1 = out;
    float* o2 = nullptr;
    float* oc = nullptr;
    if ((long long)out_size >= 3 * BH) {          // (h_new, h_new, c_new)
        o2 = out + BH;
        oc = out + 2 * BH;
    } else if ((long long)out_size >= 2 * BH) {   // (h_new, c_new)
        oc = out + BH;
    }

    cvt_f32_to_f16_kernel<<<CVT_BLOCKS, 256>>>(x, h, W, U);

    cudaFuncSetAttribute(xlstm_f16_mma_kernel,
                         cudaFuncAttributeMaxDynamicSharedMemorySize, SMEM_TOTAL);
    xlstm_f16_mma_kernel<<<2048, NTHREADS, SMEM_TOTAL>>>(c, bW, bU, o1, o2, oc);
}